// round 15
// baseline (speedup 1.0000x reference)
#include <cuda_runtime.h>
#include <cuda_bf16.h>
#include <mma.h>

using namespace nvcuda;

// EdgeNetwork:
//   P[node] = [h@W1_top | h@W1_mid]  (100000 x 384 fp32, precomputed, WMMA bf16x3)
//   out[e]  = tanh(relu(P[dst,0:192]+P[src,192:384]+dR*W1[256,:]+b1) @ W2 + b2)
// Edge phase: persistent MERGED kernel, 32-edge tiles — every warp gathers
// 4 edges (reg-resident, 48 regs) AND does MMA (16x32 strip). Next tile's
// gather issued before MMA so latency hides behind tensor work.

#define N_NODES 100000
#define E_TOTAL 640000
#define TILE_E  32
#define NTILES  (E_TOTAL / TILE_E)   // 20000
#define GRID_P  148

__device__ float gP[(size_t)N_NODES * 384];
__device__ __align__(16) unsigned short gW1h[256 * 192];  // [k][n] bf16 hi
__device__ __align__(16) unsigned short gW1l[256 * 192];
__device__ __align__(16) unsigned short gW2h[192 * 128];  // [k][n]
__device__ __align__(16) unsigned short gW2l[192 * 128];

__device__ __forceinline__ void split_bf(float v, unsigned short& hi, unsigned short& lo) {
    __nv_bfloat16 bh = __float2bfloat16(v);
    __nv_bfloat16 bl = __float2bfloat16(v - __bfloat162float(bh));
    hi = __bfloat16_as_ushort(bh);
    lo = __bfloat16_as_ushort(bl);
}
__device__ __forceinline__ unsigned pack2(unsigned short a, unsigned short b) {
    return (unsigned)a | ((unsigned)b << 16);
}
__device__ __forceinline__ unsigned cvt_bf16x2(float hi_val, float lo_val) {
    unsigned r;
    asm("cvt.rn.bf16x2.f32 %0, %1, %2;" : "=r"(r) : "f"(hi_val), "f"(lo_val));
    return r;
}
__device__ __forceinline__ float bf_lo_f32(unsigned p) {
    return __uint_as_float(p << 16);
}
__device__ __forceinline__ float bf_hi_f32(unsigned p) {
    return __uint_as_float(p & 0xffff0000u);
}
__device__ __forceinline__ float fast_tanh(float x) {
    float z = __expf(-2.0f * fabsf(x));
    float r = (1.0f - z) * __fdividef(1.0f, 1.0f + z);
    return copysignf(r, x);
}

__global__ void convert_weights(const float* __restrict__ W1,
                                const float* __restrict__ W2) {
    int i = blockIdx.x * blockDim.x + threadIdx.x;
    if (i < 256 * 192) {
        unsigned short hi, lo;
        split_bf(W1[i], hi, lo);
        gW1h[i] = hi; gW1l[i] = lo;
    } else {
        int j = i - 256 * 192;
        if (j < 192 * 128) {
            unsigned short hi, lo;
            split_bf(W2[j], hi, lo);
            gW2h[j] = hi; gW2l[j] = lo;
        }
    }
}

// ================= proj kernel: P = [h@W1_top | h@W1_mid] =================
// (byte-identical to the 684us build)
#define PJ_AH 0
#define PJ_AL 34816
#define PJ_BH 69632
#define PJ_BL 120832
#define PJ_SMEM 172032

__global__ void __launch_bounds__(256, 1)
proj_kernel(const float* __restrict__ h) {
    extern __shared__ __align__(16) unsigned char smem[];
    unsigned short* s_ah = (unsigned short*)(smem + PJ_AH);
    unsigned short* s_al = (unsigned short*)(smem + PJ_AL);
    const int tid = threadIdx.x, w = tid >> 5;
    const int m0 = blockIdx.x * 128;

    {
        const int r = tid >> 1, hk = tid & 1;
        const int m = m0 + r;
        const bool valid = m < N_NODES;
        const float4* hrow = (const float4*)(h + (size_t)m * 128) + hk * 16;
        unsigned* ah = (unsigned*)(s_ah + r * 136 + hk * 64);
        unsigned* al = (unsigned*)(s_al + r * 136 + hk * 64);
#pragma unroll
        for (int i = 0; i < 16; ++i) {
            float4 v = valid ? hrow[i] : make_float4(0.f, 0.f, 0.f, 0.f);
            unsigned short h0, l0, h1, l1, h2, l2, h3, l3;
            split_bf(v.x, h0, l0); split_bf(v.y, h1, l1);
            split_bf(v.z, h2, l2); split_bf(v.w, h3, l3);
            ah[i * 2] = pack2(h0, h1); ah[i * 2 + 1] = pack2(h2, h3);
            al[i * 2] = pack2(l0, l1); al[i * 2 + 1] = pack2(l2, l3);
        }
    }

    const bool strip_ok = (m0 + 16 * w + 16) <= N_NODES;

    for (int half = 0; half < 2; ++half) {
        __syncthreads();
        {
            const uint4* sH = (const uint4*)(gW1h + half * 128 * 192);
            const uint4* sL = (const uint4*)(gW1l + half * 128 * 192);
            uint4* dH = (uint4*)(smem + PJ_BH);
            uint4* dL = (uint4*)(smem + PJ_BL);
            for (int idx = tid; idx < 3072; idx += 256) {
                int row = idx / 24, c = idx - row * 24;
                dH[row * 25 + c] = sH[idx];
                dL[row * 25 + c] = sL[idx];
            }
        }
        __syncthreads();

        if (strip_ok) {
            wmma::fragment<wmma::accumulator, 16, 16, 16, float> acc[12];
#pragma unroll
            for (int n = 0; n < 12; ++n) wmma::fill_fragment(acc[n], 0.f);

#pragma unroll
            for (int k = 0; k < 8; ++k) {
                wmma::fragment<wmma::matrix_a, 16, 16, 16, __nv_bfloat16,
                               wmma::row_major> aH, aL;
                wmma::load_matrix_sync(aH,
                    (const __nv_bfloat16*)(s_ah + (16 * w) * 136 + k * 16), 136);
                wmma::load_matrix_sync(aL,
                    (const __nv_bfloat16*)(s_al + (16 * w) * 136 + k * 16), 136);
#pragma unroll
                for (int n = 0; n < 12; ++n) {
                    wmma::fragment<wmma::matrix_b, 16, 16, 16, __nv_bfloat16,
                                   wmma::row_major> bH, bL;
                    wmma::load_matrix_sync(bH,
                        (const __nv_bfloat16*)(smem + PJ_BH) + (k * 16) * 200 + n * 16, 200);
                    wmma::load_matrix_sync(bL,
                        (const __nv_bfloat16*)(smem + PJ_BL) + (k * 16) * 200 + n * 16, 200);
                    wmma::mma_sync(acc[n], aH, bH, acc[n]);
                    wmma::mma_sync(acc[n], aL, bH, acc[n]);
                    wmma::mma_sync(acc[n], aH, bL, acc[n]);
                }
            }
#pragma unroll
            for (int n = 0; n < 12; ++n)
                wmma::store_matrix_sync(
                    gP + (size_t)(m0 + 16 * w) * 384 + half * 192 + n * 16,
                    acc[n], 384, wmma::mem_row_major);
        }
    }
}

// ================= persistent merged edge kernel (32-edge tiles) =========
// smem: BH 0..52224 (192x136x2B), BL ..104448,
//       A image: hi 32x200x2B=12800 @104448, lo @117248 (..130048),
//       bias [16][128] f32 @130048 (8192), b1 @138240 (768), w1l @139008 (768)
#define EK_BH   0
#define EK_BL   52224
#define EK_A    104448
#define EK_ALO  12800
#define EK_BIAS 130048
#define EK_B1   138240
#define EK_W1L  139008
#define EK_SMEM 139776

__global__ void __launch_bounds__(256, 1)
edge_kernel(const float* __restrict__ dR,
            const int* __restrict__ src_idx, const int* __restrict__ dst_idx,
            const float* __restrict__ W1, const float* __restrict__ b1,
            const float* __restrict__ b2, float* __restrict__ out) {
    extern __shared__ __align__(16) unsigned char smem[];
    float* s_bias = (float*)(smem + EK_BIAS);
    float* s_b1   = (float*)(smem + EK_B1);
    float* s_w1l  = (float*)(smem + EK_W1L);

    const int tid = threadIdx.x, wid = tid >> 5, lane = tid & 31;

    // ---- one-time staging ----
    if (tid < 192) { s_b1[tid] = b1[tid]; s_w1l[tid] = W1[256 * 192 + tid]; }
    for (int idx = tid; idx < 16 * 128; idx += 256) s_bias[idx] = b2[idx & 127];
    {
        const uint4* sH = (const uint4*)gW2h;
        const uint4* sL = (const uint4*)gW2l;
        uint4* dH = (uint4*)(smem + EK_BH);
        uint4* dL = (uint4*)(smem + EK_BL);
        for (int idx = tid; idx < 3072; idx += 256) {
            int row = idx >> 4, c = idx & 15;
            dH[row * 17 + c] = sH[idx];
            dL[row * 17 + c] = sL[idx];
        }
    }
    __syncthreads();

    // gather mapping: 4 groups of 8 lanes; group g owns edge wid*4 + g
    const int g  = lane >> 3;
    const int l8 = lane & 7;
    const int er = wid * 4 + g;          // edge row within 32-row tile

    // MMA mapping: 2m x 4n (16 rows x 32 cols per warp)
    const int m0 = (wid & 1) * 16;
    const int n0 = (wid >> 1) * 32;

    unsigned short* s_ah = (unsigned short*)(smem + EK_A);
    unsigned short* s_al = (unsigned short*)(smem + EK_A + EK_ALO);

    int t = blockIdx.x;

    // ---- prime: gather tile t (regs), indices for t+GRID_P ----
    int ndc, nsc; float drc;
    int ndn, nsn; float drn;
    float4 Ar[6], Br[6];

    {
        const int e = t * TILE_E + er;
        ndc = dst_idx[e]; nsc = src_idx[e]; drc = dR[e];
        const float4* pd = (const float4*)(gP + (size_t)ndc * 384);
        const float4* ps = (const float4*)(gP + (size_t)nsc * 384 + 192);
#pragma unroll
        for (int c = 0; c < 6; ++c) Ar[c] = pd[l8 + 8 * c];
#pragma unroll
        for (int c = 0; c < 6; ++c) Br[c] = ps[l8 + 8 * c];
    }
    {
        const int t2 = t + GRID_P;
        const int tc = (t2 < NTILES) ? t2 : t;
        const int e = tc * TILE_E + er;
        ndn = dst_idx[e]; nsn = src_idx[e]; drn = dR[e];
    }

    for (; t < NTILES; t += GRID_P) {
        __syncthreads();   // previous MMA done reading A image

        // ---- convert regs -> smem A image (fuse dR/bias/relu, split hi/lo) ----
        {
            unsigned* ah = (unsigned*)((unsigned char*)s_ah + er * 400);
            unsigned* al = (unsigned*)((unsigned char*)s_al + er * 400);
#pragma unroll
            for (int c = 0; c < 6; ++c) {
                const int n = (l8 + 8 * c) * 4;
                float4 w4 = *(const float4*)(s_w1l + n);
                float4 b4 = *(const float4*)(s_b1 + n);
                float v0 = fmaxf(Ar[c].x + Br[c].x + fmaf(drc, w4.x, b4.x), 0.f);
                float v1 = fmaxf(Ar[c].y + Br[c].y + fmaf(drc, w4.y, b4.y), 0.f);
                float v2 = fmaxf(Ar[c].z + Br[c].z + fmaf(drc, w4.z, b4.z), 0.f);
                float v3 = fmaxf(Ar[c].w + Br[c].w + fmaf(drc, w4.w, b4.w), 0.f);
                unsigned hp0 = cvt_bf16x2(v1, v0);
                unsigned hp1 = cvt_bf16x2(v3, v2);
                unsigned lp0 = cvt_bf16x2(v1 - bf_hi_f32(hp0), v0 - bf_lo_f32(hp0));
                unsigned lp1 = cvt_bf16x2(v3 - bf_hi_f32(hp1), v2 - bf_lo_f32(hp1));
                *(uint2*)(ah + (l8 + 8 * c) * 2) = make_uint2(hp0, hp1);
                *(uint2*)(al + (l8 + 8 * c) * 2) = make_uint2(lp0, lp1);
            }
        }
        __syncthreads();   // A image ready

        // ---- issue next tile's gather (hides behind MMA below) ----
        const int t2 = t + GRID_P;
        if (t2 < NTILES) {
            ndc = ndn; nsc = nsn; drc = drn;
            const float4* pd = (const float4*)(gP + (size_t)ndc * 384);
            const float4* ps = (const float4*)(gP + (size_t)nsc * 384 + 192);
#pragma unroll
            for (int c = 0; c < 6; ++c) Ar[c] = pd[l8 + 8 * c];
#pragma unroll
            for (int c = 0; c < 6; ++c) Br[c] = ps[l8 + 8 * c];
            const int t3 = t2 + GRID_P;
            const int tc = (t3 < NTILES) ? t3 : t2;
            const int e = tc * TILE_E + er;
            ndn = dst_idx[e]; nsn = src_idx[e]; drn = dR[e];
        }

        // ---- MMA: 16 rows (m0) x 32 cols (n0), K=192 ----
        wmma::fragment<wmma::accumulator, 16, 16, 16, float> acc[2];
#pragma unroll
        for (int ni = 0; ni < 2; ++ni)
            wmma::load_matrix_sync(acc[ni], s_bias + n0 + ni * 16, 128,
                                   wmma::mem_row_major);

#pragma unroll
        for (int k = 0; k < 12; ++k) {
            wmma::fragment<wmma::matrix_a, 16, 16, 16, __nv_bfloat16,
                           wmma::row_major> aH, aL;
            wmma::load_matrix_sync(aH,
                (const __nv_bfloat16*)(s_ah + m0 * 200 + k * 16), 200);
            wmma::load_matrix_sync(aL,
                (const __nv_bfloat16*)(s_al + m0 * 200 + k * 16), 200);
#pragma unroll
            for (int ni = 0; ni < 2; ++ni) {
                wmma::fragment<wmma::matrix_b, 16, 16, 16, __nv_bfloat16,
                               wmma::row_major> bH, bL;
                wmma::load_matrix_sync(bH,
                    (const __nv_bfloat16*)(smem + EK_BH) + (k * 16) * 136 + n0 + ni * 16, 136);
                wmma::load_matrix_sync(bL,
                    (const __nv_bfloat16*)(smem + EK_BL) + (k * 16) * 136 + n0 + ni * 16, 136);
                wmma::mma_sync(acc[ni], aH, bH, acc[ni]);
                wmma::mma_sync(acc[ni], aL, bH, acc[ni]);
                wmma::mma_sync(acc[ni], aH, bL, acc[ni]);
            }
        }

        // ---- epilogue: tanh + store ----
        const int e0 = t * TILE_E;
#pragma unroll
        for (int ni = 0; ni < 2; ++ni) {
#pragma unroll
            for (int x = 0; x < acc[ni].num_elements; ++x)
                acc[ni].x[x] = fast_tanh(acc[ni].x[x]);
            wmma::store_matrix_sync(out + (size_t)(e0 + m0) * 128 + n0 + ni * 16,
                                    acc[ni], 128, wmma::mem_row_major);
        }
    }
}

extern "C" void kernel_launch(void* const* d_in, const int* in_sizes, int n_in,
                              void* d_out, int out_size) {
    const float* h   = (const float*)d_in[0];
    const float* dR  = (const float*)d_in[1];
    const int*   src = (const int*)  d_in[2];
    const int*   dst = (const int*)  d_in[3];
    const float* W1  = (const float*)d_in[4];
    const float* b1  = (const float*)d_in[5];
    const float* W2  = (const float*)d_in[6];
    const float* b2  = (const float*)d_in[7];
    float* out = (float*)d_out;

    convert_weights<<<288, 256>>>(W1, W2);

    cudaFuncSetAttribute(proj_kernel,
                         cudaFuncAttributeMaxDynamicSharedMemorySize, PJ_SMEM);
    cudaFuncSetAttribute(edge_kernel,
                         cudaFuncAttributeMaxDynamicSharedMemorySize, EK_SMEM);

    proj_kernel<<<(N_NODES + 127) / 128, 256, PJ_SMEM>>>(h);
    edge_kernel<<<GRID_P, 256, EK_SMEM>>>(dR, src, dst, W1, b1, b2, out);
}

// round 16
// speedup vs baseline: 1.2216x; 1.2216x over previous
#include <cuda_runtime.h>
#include <cuda_bf16.h>
#include <mma.h>

using namespace nvcuda;

// EdgeNetwork:
//   P[node] = [h@W1_top | h@W1_mid]  (100000 x 384 fp32, precomputed, WMMA bf16x3)
//   out[e]  = tanh(relu(P[dst,0:192]+P[src,192:384]+dR*W1[256,:]+b1) @ W2 + b2)
// Edge phase: persistent warp-specialized pipeline (the proven 684us shape)
// + L2 software prefetch of gather rows TWO tiles ahead (prefetch.global.L2).

#define N_NODES 100000
#define E_TOTAL 640000
#define NTILES  (E_TOTAL / 64)     // 10000
#define GRID_P  148

__device__ float gP[(size_t)N_NODES * 384];
__device__ __align__(16) unsigned short gW1h[256 * 192];  // [k][n] bf16 hi
__device__ __align__(16) unsigned short gW1l[256 * 192];
__device__ __align__(16) unsigned short gW2h[192 * 128];  // [k][n]
__device__ __align__(16) unsigned short gW2l[192 * 128];

__device__ __forceinline__ void split_bf(float v, unsigned short& hi, unsigned short& lo) {
    __nv_bfloat16 bh = __float2bfloat16(v);
    __nv_bfloat16 bl = __float2bfloat16(v - __bfloat162float(bh));
    hi = __bfloat16_as_ushort(bh);
    lo = __bfloat16_as_ushort(bl);
}
__device__ __forceinline__ unsigned pack2(unsigned short a, unsigned short b) {
    return (unsigned)a | ((unsigned)b << 16);
}
__device__ __forceinline__ unsigned cvt_bf16x2(float hi_val, float lo_val) {
    unsigned r;
    asm("cvt.rn.bf16x2.f32 %0, %1, %2;" : "=r"(r) : "f"(hi_val), "f"(lo_val));
    return r;
}
__device__ __forceinline__ float bf_lo_f32(unsigned p) {
    return __uint_as_float(p << 16);
}
__device__ __forceinline__ float bf_hi_f32(unsigned p) {
    return __uint_as_float(p & 0xffff0000u);
}
__device__ __forceinline__ void bar_sync(int id) {
    asm volatile("bar.sync %0, 256;" :: "r"(id) : "memory");
}
__device__ __forceinline__ void bar_arrive(int id) {
    asm volatile("bar.arrive %0, 256;" :: "r"(id) : "memory");
}
__device__ __forceinline__ void l2_prefetch(const void* p) {
    asm volatile("prefetch.global.L2 [%0];" :: "l"(p));
}
__device__ __forceinline__ float fast_tanh(float x) {
    float z = __expf(-2.0f * fabsf(x));
    float r = (1.0f - z) * __fdividef(1.0f, 1.0f + z);
    return copysignf(r, x);
}

__global__ void convert_weights(const float* __restrict__ W1,
                                const float* __restrict__ W2) {
    int i = blockIdx.x * blockDim.x + threadIdx.x;
    if (i < 256 * 192) {
        unsigned short hi, lo;
        split_bf(W1[i], hi, lo);
        gW1h[i] = hi; gW1l[i] = lo;
    } else {
        int j = i - 256 * 192;
        if (j < 192 * 128) {
            unsigned short hi, lo;
            split_bf(W2[j], hi, lo);
            gW2h[j] = hi; gW2l[j] = lo;
        }
    }
}

// ================= proj kernel: P = [h@W1_top | h@W1_mid] =================
// (byte-identical to the 684us build)
#define PJ_AH 0
#define PJ_AL 34816
#define PJ_BH 69632
#define PJ_BL 120832
#define PJ_SMEM 172032

__global__ void __launch_bounds__(256, 1)
proj_kernel(const float* __restrict__ h) {
    extern __shared__ __align__(16) unsigned char smem[];
    unsigned short* s_ah = (unsigned short*)(smem + PJ_AH);
    unsigned short* s_al = (unsigned short*)(smem + PJ_AL);
    const int tid = threadIdx.x, w = tid >> 5;
    const int m0 = blockIdx.x * 128;

    {
        const int r = tid >> 1, hk = tid & 1;
        const int m = m0 + r;
        const bool valid = m < N_NODES;
        const float4* hrow = (const float4*)(h + (size_t)m * 128) + hk * 16;
        unsigned* ah = (unsigned*)(s_ah + r * 136 + hk * 64);
        unsigned* al = (unsigned*)(s_al + r * 136 + hk * 64);
#pragma unroll
        for (int i = 0; i < 16; ++i) {
            float4 v = valid ? hrow[i] : make_float4(0.f, 0.f, 0.f, 0.f);
            unsigned short h0, l0, h1, l1, h2, l2, h3, l3;
            split_bf(v.x, h0, l0); split_bf(v.y, h1, l1);
            split_bf(v.z, h2, l2); split_bf(v.w, h3, l3);
            ah[i * 2] = pack2(h0, h1); ah[i * 2 + 1] = pack2(h2, h3);
            al[i * 2] = pack2(l0, l1); al[i * 2 + 1] = pack2(l2, l3);
        }
    }

    const bool strip_ok = (m0 + 16 * w + 16) <= N_NODES;

    for (int half = 0; half < 2; ++half) {
        __syncthreads();
        {
            const uint4* sH = (const uint4*)(gW1h + half * 128 * 192);
            const uint4* sL = (const uint4*)(gW1l + half * 128 * 192);
            uint4* dH = (uint4*)(smem + PJ_BH);
            uint4* dL = (uint4*)(smem + PJ_BL);
            for (int idx = tid; idx < 3072; idx += 256) {
                int row = idx / 24, c = idx - row * 24;
                dH[row * 25 + c] = sH[idx];
                dL[row * 25 + c] = sL[idx];
            }
        }
        __syncthreads();

        if (strip_ok) {
            wmma::fragment<wmma::accumulator, 16, 16, 16, float> acc[12];
#pragma unroll
            for (int n = 0; n < 12; ++n) wmma::fill_fragment(acc[n], 0.f);

#pragma unroll
            for (int k = 0; k < 8; ++k) {
                wmma::fragment<wmma::matrix_a, 16, 16, 16, __nv_bfloat16,
                               wmma::row_major> aH, aL;
                wmma::load_matrix_sync(aH,
                    (const __nv_bfloat16*)(s_ah + (16 * w) * 136 + k * 16), 136);
                wmma::load_matrix_sync(aL,
                    (const __nv_bfloat16*)(s_al + (16 * w) * 136 + k * 16), 136);
#pragma unroll
                for (int n = 0; n < 12; ++n) {
                    wmma::fragment<wmma::matrix_b, 16, 16, 16, __nv_bfloat16,
                                   wmma::row_major> bH, bL;
                    wmma::load_matrix_sync(bH,
                        (const __nv_bfloat16*)(smem + PJ_BH) + (k * 16) * 200 + n * 16, 200);
                    wmma::load_matrix_sync(bL,
                        (const __nv_bfloat16*)(smem + PJ_BL) + (k * 16) * 200 + n * 16, 200);
                    wmma::mma_sync(acc[n], aH, bH, acc[n]);
                    wmma::mma_sync(acc[n], aL, bH, acc[n]);
                    wmma::mma_sync(acc[n], aH, bL, acc[n]);
                }
            }
#pragma unroll
            for (int n = 0; n < 12; ++n)
                wmma::store_matrix_sync(
                    gP + (size_t)(m0 + 16 * w) * 384 + half * 192 + n * 16,
                    acc[n], 384, wmma::mem_row_major);
        }
    }
}

// ================= persistent edge kernel =================
#define EK_BH   0
#define EK_BL   52224
#define EK_A0   104448
#define EK_ABUF 51200
#define EK_ALO  25600
#define EK_BIAS 206848
#define EK_B1   215040
#define EK_W1L  215808
#define EK_SMEM 216576

__global__ void __launch_bounds__(256, 1)
edge_kernel(const float* __restrict__ dR,
            const int* __restrict__ src_idx, const int* __restrict__ dst_idx,
            const float* __restrict__ W1, const float* __restrict__ b1,
            const float* __restrict__ b2, float* __restrict__ out) {
    extern __shared__ __align__(16) unsigned char smem[];
    float* s_bias = (float*)(smem + EK_BIAS);
    float* s_b1   = (float*)(smem + EK_B1);
    float* s_w1l  = (float*)(smem + EK_W1L);

    const int tid = threadIdx.x, wid = tid >> 5;

    if (tid < 192) { s_b1[tid] = b1[tid]; s_w1l[tid] = W1[256 * 192 + tid]; }
    for (int idx = tid; idx < 16 * 128; idx += 256) s_bias[idx] = b2[idx & 127];
    {
        const uint4* sH = (const uint4*)gW2h;
        const uint4* sL = (const uint4*)gW2l;
        uint4* dH = (uint4*)(smem + EK_BH);
        uint4* dL = (uint4*)(smem + EK_BL);
        for (int idx = tid; idx < 3072; idx += 256) {
            int row = idx >> 4, c = idx & 15;
            dH[row * 17 + c] = sH[idx];
            dL[row * 17 + c] = sL[idx];
        }
    }
    __syncthreads();

    // barrier ids: full[b] = 1+b, empty[b] = 3+b
    if (wid < 4) {
        // ================= producers (threads 0..127) =================
        // 8-lane groups; group g owns edge erb + rd*4; lane l8 reads chunk l8+8c.
        const int lane = tid & 31;
        const int g   = lane >> 3;
        const int l8  = lane & 7;
        const int erb = wid * 16 + g;

        // 3-deep index pipeline: cur (t), nxt (t+1, data prefetched), nx2 (t+2)
        int nd[4], ns[4];   float dr[4];
        int ndn[4], nsn[4]; float drn[4];
        int ndm[4], nsm[4]; float drm[4];

        const int t0 = blockIdx.x;
        {
#pragma unroll
            for (int rd = 0; rd < 4; ++rd) {
                const int e = t0 * 64 + erb + rd * 4;
                nd[rd] = dst_idx[e]; ns[rd] = src_idx[e]; dr[rd] = dR[e];
            }
            const int t1 = t0 + GRID_P;
            const int tc = (t1 < NTILES) ? t1 : t0;
#pragma unroll
            for (int rd = 0; rd < 4; ++rd) {
                const int e = tc * 64 + erb + rd * 4;
                ndn[rd] = dst_idx[e]; nsn[rd] = src_idx[e]; drn[rd] = dR[e];
            }
            // prefetch t+1's data into L2 (lead = whole tile t0)
            if (l8 < 6) {
#pragma unroll
                for (int rd = 0; rd < 4; ++rd) {
                    l2_prefetch(gP + (size_t)ndn[rd] * 384 + l8 * 32);
                    l2_prefetch(gP + (size_t)nsn[rd] * 384 + 192 + l8 * 32);
                }
            }
        }

        int i = 0;
        for (int t = t0; t < NTILES; t += GRID_P, ++i) {
            // issue index loads for t+2 (consumed at end of this tile)
            {
                const int t2 = t + 2 * GRID_P;
                const int tc = (t2 < NTILES) ? t2 : t;
#pragma unroll
                for (int rd = 0; rd < 4; ++rd) {
                    const int e = tc * 64 + erb + rd * 4;
                    ndm[rd] = dst_idx[e]; nsm[rd] = src_idx[e]; drm[rd] = dR[e];
                }
            }

            const int buf = i & 1;
            if (i >= 2) bar_sync(3 + buf);
            unsigned char* abase = smem + EK_A0 + buf * EK_ABUF;

            float4 Ad[2][6], Bd[2][6];
            {
                const float4* pd = (const float4*)(gP + (size_t)nd[0] * 384);
                const float4* ps = (const float4*)(gP + (size_t)ns[0] * 384 + 192);
#pragma unroll
                for (int c = 0; c < 6; ++c) { Ad[0][c] = pd[l8 + 8 * c]; }
#pragma unroll
                for (int c = 0; c < 6; ++c) { Bd[0][c] = ps[l8 + 8 * c]; }
            }

#pragma unroll
            for (int rd = 0; rd < 4; ++rd) {
                const int p = rd & 1;
                if (rd < 3) {   // preload next round into other parity
                    const float4* pd = (const float4*)(gP + (size_t)nd[rd + 1] * 384);
                    const float4* ps = (const float4*)(gP + (size_t)ns[rd + 1] * 384 + 192);
#pragma unroll
                    for (int c = 0; c < 6; ++c) { Ad[p ^ 1][c] = pd[l8 + 8 * c]; }
#pragma unroll
                    for (int c = 0; c < 6; ++c) { Bd[p ^ 1][c] = ps[l8 + 8 * c]; }
                }
                const int er = erb + rd * 4;
                unsigned* ah = (unsigned*)(abase + er * 400);
                unsigned* al = (unsigned*)(abase + EK_ALO + er * 400);
                const float drv = dr[rd];
#pragma unroll
                for (int c = 0; c < 6; ++c) {
                    const int n = (l8 + 8 * c) * 4;
                    float4 w4 = *(const float4*)(s_w1l + n);
                    float4 b4 = *(const float4*)(s_b1 + n);
                    float v0 = fmaxf(Ad[p][c].x + Bd[p][c].x + fmaf(drv, w4.x, b4.x), 0.f);
                    float v1 = fmaxf(Ad[p][c].y + Bd[p][c].y + fmaf(drv, w4.y, b4.y), 0.f);
                    float v2 = fmaxf(Ad[p][c].z + Bd[p][c].z + fmaf(drv, w4.z, b4.z), 0.f);
                    float v3 = fmaxf(Ad[p][c].w + Bd[p][c].w + fmaf(drv, w4.w, b4.w), 0.f);
                    unsigned hp0 = cvt_bf16x2(v1, v0);
                    unsigned hp1 = cvt_bf16x2(v3, v2);
                    unsigned lp0 = cvt_bf16x2(v1 - bf_hi_f32(hp0), v0 - bf_lo_f32(hp0));
                    unsigned lp1 = cvt_bf16x2(v3 - bf_hi_f32(hp1), v2 - bf_lo_f32(hp1));
                    *(uint2*)(ah + (l8 + 8 * c) * 2) = make_uint2(hp0, hp1);
                    *(uint2*)(al + (l8 + 8 * c) * 2) = make_uint2(lp0, lp1);
                }
            }
            __threadfence_block();
            bar_arrive(1 + buf);

            // prefetch t+2's data into L2 (lead = whole tile t+1)
            if (l8 < 6) {
#pragma unroll
                for (int rd = 0; rd < 4; ++rd) {
                    l2_prefetch(gP + (size_t)ndm[rd] * 384 + l8 * 32);
                    l2_prefetch(gP + (size_t)nsm[rd] * 384 + 192 + l8 * 32);
                }
            }

            // rotate index pipeline
#pragma unroll
            for (int rd = 0; rd < 4; ++rd) {
                nd[rd] = ndn[rd]; ns[rd] = nsn[rd]; dr[rd] = drn[rd];
                ndn[rd] = ndm[rd]; nsn[rd] = nsm[rd]; drn[rd] = drm[rd];
            }
        }
    } else {
        // ================= consumers (threads 128..255) =================
        const int cw = wid - 4;
        const int m0 = (cw & 1) * 32;
        const int n0 = (cw >> 1) * 64;
        int i = 0;
        for (int t = blockIdx.x; t < NTILES; t += GRID_P, ++i) {
            const int buf = i & 1;
            bar_sync(1 + buf);

            const unsigned short* aBase =
                (const unsigned short*)(smem + EK_A0 + buf * EK_ABUF);

            wmma::fragment<wmma::accumulator, 16, 16, 16, float> acc[2][4];
#pragma unroll
            for (int mi = 0; mi < 2; ++mi)
#pragma unroll
                for (int ni = 0; ni < 4; ++ni)
                    wmma::load_matrix_sync(acc[mi][ni],
                        s_bias + n0 + ni * 16, 128, wmma::mem_row_major);

#pragma unroll
            for (int k = 0; k < 12; ++k) {
                wmma::fragment<wmma::matrix_a, 16, 16, 16, __nv_bfloat16,
                               wmma::row_major> aH[2], aL[2];
#pragma unroll
                for (int mi = 0; mi < 2; ++mi) {
                    wmma::load_matrix_sync(aH[mi],
                        (const __nv_bfloat16*)(aBase + (m0 + mi * 16) * 200 + k * 16), 200);
                    wmma::load_matrix_sync(aL[mi],
                        (const __nv_bfloat16*)(aBase + 12800 + (m0 + mi * 16) * 200 + k * 16), 200);
                }
#pragma unroll
                for (int ni = 0; ni < 4; ++ni) {
                    wmma::fragment<wmma::matrix_b, 16, 16, 16, __nv_bfloat16,
                                   wmma::row_major> bH, bL;
                    wmma::load_matrix_sync(bH,
                        (const __nv_bfloat16*)(smem + EK_BH) + (k * 16) * 136 + n0 + ni * 16, 136);
                    wmma::load_matrix_sync(bL,
                        (const __nv_bfloat16*)(smem + EK_BL) + (k * 16) * 136 + n0 + ni * 16, 136);
#pragma unroll
                    for (int mi = 0; mi < 2; ++mi) {
                        wmma::mma_sync(acc[mi][ni], aH[mi], bH, acc[mi][ni]);
                        wmma::mma_sync(acc[mi][ni], aL[mi], bH, acc[mi][ni]);
                        wmma::mma_sync(acc[mi][ni], aH[mi], bL, acc[mi][ni]);
                    }
                }
            }
            __threadfence_block();
            bar_arrive(3 + buf);

            const int e0 = t * 64;
#pragma unroll
            for (int mi = 0; mi < 2; ++mi)
#pragma unroll
                for (int ni = 0; ni < 4; ++ni) {
#pragma unroll
                    for (int x = 0; x < acc[mi][ni].num_elements; ++x)
                        acc[mi][ni].x[x] = fast_tanh(acc[mi][ni].x[x]);
                    wmma::store_matrix_sync(
                        out + (size_t)(e0 + m0 + mi * 16) * 128 + n0 + ni * 16,
                        acc[mi][ni], 128, wmma::mem_row_major);
                }
        }
    }
}

extern "C" void kernel_launch(void* const* d_in, const int* in_sizes, int n_in,
                              void* d_out, int out_size) {
    const float* h   = (const float*)d_in[0];
    const float* dR  = (const float*)d_in[1];
    const int*   src = (const int*)  d_in[2];
    const int*   dst = (const int*)  d_in[3];
    const float* W1  = (const float*)d_in[4];
    const float* b1  = (const float*)d_in[5];
    const float* W2  = (const float*)d_in[6];
    const float* b2  = (const float*)d_in[7];
    float* out = (float*)d_out;

    convert_weights<<<288, 256>>>(W1, W2);

    cudaFuncSetAttribute(proj_kernel,
                         cudaFuncAttributeMaxDynamicSharedMemorySize, PJ_SMEM);
    cudaFuncSetAttribute(edge_kernel,
                         cudaFuncAttributeMaxDynamicSharedMemorySize, EK_SMEM);

    proj_kernel<<<(N_NODES + 127) / 128, 256, PJ_SMEM>>>(h);
    edge_kernel<<<GRID_P, 256, EK_SMEM>>>(dR, src, dst, W1, b1, b2, out);
}

// round 17
// speedup vs baseline: 1.6815x; 1.3765x over previous
#include <cuda_runtime.h>
#include <cuda_bf16.h>
#include <cuda_fp16.h>
#include <mma.h>

using namespace nvcuda;

// EdgeNetwork:
//   P[node] = [h@W1_top | h@W1_mid]  (100000 x 384 fp32, precomputed, WMMA bf16x3)
//   out[e]  = tanh(relu(P[dst,0:192]+P[src,192:384]+dR*W1[256,:]+b1) @ W2 + b2)
// GEMM2 in fp16: hid single-fp16 (2^-12), W2 fp16 hi/lo split (exact) ->
// 2 MMA products instead of 3, producer residual work eliminated.

#define N_NODES 100000
#define E_TOTAL 640000
#define NTILES  (E_TOTAL / 64)     // 10000
#define GRID_P  148

__device__ float gP[(size_t)N_NODES * 384];
__device__ __align__(16) unsigned short gW1h[256 * 192];  // [k][n] bf16 hi
__device__ __align__(16) unsigned short gW1l[256 * 192];
__device__ __align__(16) unsigned short gW2h[192 * 128];  // [k][n] fp16 hi
__device__ __align__(16) unsigned short gW2l[192 * 128];  // [k][n] fp16 lo

__device__ __forceinline__ void split_bf(float v, unsigned short& hi, unsigned short& lo) {
    __nv_bfloat16 bh = __float2bfloat16(v);
    __nv_bfloat16 bl = __float2bfloat16(v - __bfloat162float(bh));
    hi = __bfloat16_as_ushort(bh);
    lo = __bfloat16_as_ushort(bl);
}
__device__ __forceinline__ unsigned pack2(unsigned short a, unsigned short b) {
    return (unsigned)a | ((unsigned)b << 16);
}
// pack two fp32 -> f16x2 (second arg -> low half), round-to-nearest
__device__ __forceinline__ unsigned cvt_f16x2(float hi_val, float lo_val) {
    unsigned r;
    asm("cvt.rn.f16x2.f32 %0, %1, %2;" : "=r"(r) : "f"(hi_val), "f"(lo_val));
    return r;
}
__device__ __forceinline__ void bar_sync(int id) {
    asm volatile("bar.sync %0, 256;" :: "r"(id) : "memory");
}
__device__ __forceinline__ void bar_arrive(int id) {
    asm volatile("bar.arrive %0, 256;" :: "r"(id) : "memory");
}
__device__ __forceinline__ void l2_prefetch(const void* p) {
    asm volatile("prefetch.global.L2 [%0];" :: "l"(p));
}
__device__ __forceinline__ float fast_tanh(float x) {
    float z = __expf(-2.0f * fabsf(x));
    float r = (1.0f - z) * __fdividef(1.0f, 1.0f + z);
    return copysignf(r, x);
}

__global__ void convert_weights(const float* __restrict__ W1,
                                const float* __restrict__ W2) {
    int i = blockIdx.x * blockDim.x + threadIdx.x;
    if (i < 256 * 192) {
        unsigned short hi, lo;
        split_bf(W1[i], hi, lo);
        gW1h[i] = hi; gW1l[i] = lo;
    } else {
        int j = i - 256 * 192;
        if (j < 192 * 128) {
            float v = W2[j];
            __half hh = __float2half_rn(v);
            __half hl = __float2half_rn(v - __half2float(hh));
            gW2h[j] = __half_as_ushort(hh);
            gW2l[j] = __half_as_ushort(hl);
        }
    }
}

// ================= proj kernel: P = [h@W1_top | h@W1_mid] =================
// (byte-identical to the 663us build — bf16x3, fp32 P)
#define PJ_AH 0
#define PJ_AL 34816
#define PJ_BH 69632
#define PJ_BL 120832
#define PJ_SMEM 172032

__global__ void __launch_bounds__(256, 1)
proj_kernel(const float* __restrict__ h) {
    extern __shared__ __align__(16) unsigned char smem[];
    unsigned short* s_ah = (unsigned short*)(smem + PJ_AH);
    unsigned short* s_al = (unsigned short*)(smem + PJ_AL);
    const int tid = threadIdx.x, w = tid >> 5;
    const int m0 = blockIdx.x * 128;

    {
        const int r = tid >> 1, hk = tid & 1;
        const int m = m0 + r;
        const bool valid = m < N_NODES;
        const float4* hrow = (const float4*)(h + (size_t)m * 128) + hk * 16;
        unsigned* ah = (unsigned*)(s_ah + r * 136 + hk * 64);
        unsigned* al = (unsigned*)(s_al + r * 136 + hk * 64);
#pragma unroll
        for (int i = 0; i < 16; ++i) {
            float4 v = valid ? hrow[i] : make_float4(0.f, 0.f, 0.f, 0.f);
            unsigned short h0, l0, h1, l1, h2, l2, h3, l3;
            split_bf(v.x, h0, l0); split_bf(v.y, h1, l1);
            split_bf(v.z, h2, l2); split_bf(v.w, h3, l3);
            ah[i * 2] = pack2(h0, h1); ah[i * 2 + 1] = pack2(h2, h3);
            al[i * 2] = pack2(l0, l1); al[i * 2 + 1] = pack2(l2, l3);
        }
    }

    const bool strip_ok = (m0 + 16 * w + 16) <= N_NODES;

    for (int half = 0; half < 2; ++half) {
        __syncthreads();
        {
            const uint4* sH = (const uint4*)(gW1h + half * 128 * 192);
            const uint4* sL = (const uint4*)(gW1l + half * 128 * 192);
            uint4* dH = (uint4*)(smem + PJ_BH);
            uint4* dL = (uint4*)(smem + PJ_BL);
            for (int idx = tid; idx < 3072; idx += 256) {
                int row = idx / 24, c = idx - row * 24;
                dH[row * 25 + c] = sH[idx];
                dL[row * 25 + c] = sL[idx];
            }
        }
        __syncthreads();

        if (strip_ok) {
            wmma::fragment<wmma::accumulator, 16, 16, 16, float> acc[12];
#pragma unroll
            for (int n = 0; n < 12; ++n) wmma::fill_fragment(acc[n], 0.f);

#pragma unroll
            for (int k = 0; k < 8; ++k) {
                wmma::fragment<wmma::matrix_a, 16, 16, 16, __nv_bfloat16,
                               wmma::row_major> aH, aL;
                wmma::load_matrix_sync(aH,
                    (const __nv_bfloat16*)(s_ah + (16 * w) * 136 + k * 16), 136);
                wmma::load_matrix_sync(aL,
                    (const __nv_bfloat16*)(s_al + (16 * w) * 136 + k * 16), 136);
#pragma unroll
                for (int n = 0; n < 12; ++n) {
                    wmma::fragment<wmma::matrix_b, 16, 16, 16, __nv_bfloat16,
                                   wmma::row_major> bH, bL;
                    wmma::load_matrix_sync(bH,
                        (const __nv_bfloat16*)(smem + PJ_BH) + (k * 16) * 200 + n * 16, 200);
                    wmma::load_matrix_sync(bL,
                        (const __nv_bfloat16*)(smem + PJ_BL) + (k * 16) * 200 + n * 16, 200);
                    wmma::mma_sync(acc[n], aH, bH, acc[n]);
                    wmma::mma_sync(acc[n], aL, bH, acc[n]);
                    wmma::mma_sync(acc[n], aH, bL, acc[n]);
                }
            }
#pragma unroll
            for (int n = 0; n < 12; ++n)
                wmma::store_matrix_sync(
                    gP + (size_t)(m0 + 16 * w) * 384 + half * 192 + n * 16,
                    acc[n], 384, wmma::mem_row_major);
        }
    }
}

// ================= persistent edge kernel (fp16 GEMM2) =================
// smem: BH 0..52224 (192x136 fp16), BL ..104448,
//       A bufs (fp16, single image): 2 x 64x200x2B=25600 @104448 (..155648)
//       bias [16][128] f32 @155648 (8192), b1 @163840 (768), w1l @164608 (768)
#define EK_BH   0
#define EK_BL   52224
#define EK_A0   104448
#define EK_ABUF 25600
#define EK_BIAS 155648
#define EK_B1   163840
#define EK_W1L  164608
#define EK_SMEM 165376

__global__ void __launch_bounds__(256, 1)
edge_kernel(const float* __restrict__ dR,
            const int* __restrict__ src_idx, const int* __restrict__ dst_idx,
            const float* __restrict__ W1, const float* __restrict__ b1,
            const float* __restrict__ b2, float* __restrict__ out) {
    extern __shared__ __align__(16) unsigned char smem[];
    float* s_bias = (float*)(smem + EK_BIAS);
    float* s_b1   = (float*)(smem + EK_B1);
    float* s_w1l  = (float*)(smem + EK_W1L);

    const int tid = threadIdx.x, wid = tid >> 5;

    if (tid < 192) { s_b1[tid] = b1[tid]; s_w1l[tid] = W1[256 * 192 + tid]; }
    for (int idx = tid; idx < 16 * 128; idx += 256) s_bias[idx] = b2[idx & 127];
    {
        const uint4* sH = (const uint4*)gW2h;
        const uint4* sL = (const uint4*)gW2l;
        uint4* dH = (uint4*)(smem + EK_BH);
        uint4* dL = (uint4*)(smem + EK_BL);
        for (int idx = tid; idx < 3072; idx += 256) {
            int row = idx >> 4, c = idx & 15;
            dH[row * 17 + c] = sH[idx];
            dL[row * 17 + c] = sL[idx];
        }
    }
    __syncthreads();

    // barrier ids: full[b] = 1+b, empty[b] = 3+b
    if (wid < 4) {
        // ================= producers (threads 0..127) =================
        const int lane = tid & 31;
        const int g   = lane >> 3;
        const int l8  = lane & 7;
        const int erb = wid * 16 + g;

        int nd[4], ns[4];   float dr[4];
        int ndn[4], nsn[4]; float drn[4];
        int ndm[4], nsm[4]; float drm[4];

        const int t0 = blockIdx.x;
        {
#pragma unroll
            for (int rd = 0; rd < 4; ++rd) {
                const int e = t0 * 64 + erb + rd * 4;
                nd[rd] = dst_idx[e]; ns[rd] = src_idx[e]; dr[rd] = dR[e];
            }
            const int t1 = t0 + GRID_P;
            const int tc = (t1 < NTILES) ? t1 : t0;
#pragma unroll
            for (int rd = 0; rd < 4; ++rd) {
                const int e = tc * 64 + erb + rd * 4;
                ndn[rd] = dst_idx[e]; nsn[rd] = src_idx[e]; drn[rd] = dR[e];
            }
            if (l8 < 6) {
#pragma unroll
                for (int rd = 0; rd < 4; ++rd) {
                    l2_prefetch(gP + (size_t)ndn[rd] * 384 + l8 * 32);
                    l2_prefetch(gP + (size_t)nsn[rd] * 384 + 192 + l8 * 32);
                }
            }
        }

        int i = 0;
        for (int t = t0; t < NTILES; t += GRID_P, ++i) {
            {
                const int t2 = t + 2 * GRID_P;
                const int tc = (t2 < NTILES) ? t2 : t;
#pragma unroll
                for (int rd = 0; rd < 4; ++rd) {
                    const int e = tc * 64 + erb + rd * 4;
                    ndm[rd] = dst_idx[e]; nsm[rd] = src_idx[e]; drm[rd] = dR[e];
                }
            }

            const int buf = i & 1;
            if (i >= 2) bar_sync(3 + buf);
            unsigned char* abase = smem + EK_A0 + buf * EK_ABUF;

            float4 Ad[2][6], Bd[2][6];
            {
                const float4* pd = (const float4*)(gP + (size_t)nd[0] * 384);
                const float4* ps = (const float4*)(gP + (size_t)ns[0] * 384 + 192);
#pragma unroll
                for (int c = 0; c < 6; ++c) { Ad[0][c] = pd[l8 + 8 * c]; }
#pragma unroll
                for (int c = 0; c < 6; ++c) { Bd[0][c] = ps[l8 + 8 * c]; }
            }

#pragma unroll
            for (int rd = 0; rd < 4; ++rd) {
                const int p = rd & 1;
                if (rd < 3) {
                    const float4* pd = (const float4*)(gP + (size_t)nd[rd + 1] * 384);
                    const float4* ps = (const float4*)(gP + (size_t)ns[rd + 1] * 384 + 192);
#pragma unroll
                    for (int c = 0; c < 6; ++c) { Ad[p ^ 1][c] = pd[l8 + 8 * c]; }
#pragma unroll
                    for (int c = 0; c < 6; ++c) { Bd[p ^ 1][c] = ps[l8 + 8 * c]; }
                }
                const int er = erb + rd * 4;
                unsigned* ah = (unsigned*)(abase + er * 400);
                const float drv = dr[rd];
#pragma unroll
                for (int c = 0; c < 6; ++c) {
                    const int n = (l8 + 8 * c) * 4;
                    float4 w4 = *(const float4*)(s_w1l + n);
                    float4 b4 = *(const float4*)(s_b1 + n);
                    float v0 = fmaxf(Ad[p][c].x + Bd[p][c].x + fmaf(drv, w4.x, b4.x), 0.f);
                    float v1 = fmaxf(Ad[p][c].y + Bd[p][c].y + fmaf(drv, w4.y, b4.y), 0.f);
                    float v2 = fmaxf(Ad[p][c].z + Bd[p][c].z + fmaf(drv, w4.z, b4.z), 0.f);
                    float v3 = fmaxf(Ad[p][c].w + Bd[p][c].w + fmaf(drv, w4.w, b4.w), 0.f);
                    unsigned hp0 = cvt_f16x2(v1, v0);
                    unsigned hp1 = cvt_f16x2(v3, v2);
                    *(uint2*)(ah + (l8 + 8 * c) * 2) = make_uint2(hp0, hp1);
                }
            }
            __threadfence_block();
            bar_arrive(1 + buf);

            if (l8 < 6) {
#pragma unroll
                for (int rd = 0; rd < 4; ++rd) {
                    l2_prefetch(gP + (size_t)ndm[rd] * 384 + l8 * 32);
                    l2_prefetch(gP + (size_t)nsm[rd] * 384 + 192 + l8 * 32);
                }
            }

#pragma unroll
            for (int rd = 0; rd < 4; ++rd) {
                nd[rd] = ndn[rd]; ns[rd] = nsn[rd]; dr[rd] = drn[rd];
                ndn[rd] = ndm[rd]; nsn[rd] = nsm[rd]; drn[rd] = drm[rd];
            }
        }
    } else {
        // ================= consumers (threads 128..255) =================
        const int cw = wid - 4;
        const int m0 = (cw & 1) * 32;
        const int n0 = (cw >> 1) * 64;
        int i = 0;
        for (int t = blockIdx.x; t < NTILES; t += GRID_P, ++i) {
            const int buf = i & 1;
            bar_sync(1 + buf);

            const __half* aBase = (const __half*)(smem + EK_A0 + buf * EK_ABUF);

            wmma::fragment<wmma::accumulator, 16, 16, 16, float> acc[2][4];
#pragma unroll
            for (int mi = 0; mi < 2; ++mi)
#pragma unroll
                for (int ni = 0; ni < 4; ++ni)
                    wmma::load_matrix_sync(acc[mi][ni],
                        s_bias + n0 + ni * 16, 128, wmma::mem_row_major);

#pragma unroll
            for (int k = 0; k < 12; ++k) {
                wmma::fragment<wmma::matrix_a, 16, 16, 16, __half,
                               wmma::row_major> aH[2];
#pragma unroll
                for (int mi = 0; mi < 2; ++mi)
                    wmma::load_matrix_sync(aH[mi],
                        aBase + (m0 + mi * 16) * 200 + k * 16, 200);
#pragma unroll
                for (int ni = 0; ni < 4; ++ni) {
                    wmma::fragment<wmma::matrix_b, 16, 16, 16, __half,
                                   wmma::row_major> bH, bL;
                    wmma::load_matrix_sync(bH,
                        (const __half*)(smem + EK_BH) + (k * 16) * 136 + n0 + ni * 16, 136);
                    wmma::load_matrix_sync(bL,
                        (const __half*)(smem + EK_BL) + (k * 16) * 136 + n0 + ni * 16, 136);
#pragma unroll
                    for (int mi = 0; mi < 2; ++mi) {
                        wmma::mma_sync(acc[mi][ni], aH[mi], bH, acc[mi][ni]);
                        wmma::mma_sync(acc[mi][ni], aH[mi], bL, acc[mi][ni]);
                    }
                }
            }
            __threadfence_block();
            bar_arrive(3 + buf);

            const int e0 = t * 64;
#pragma unroll
            for (int mi = 0; mi < 2; ++mi)
#pragma unroll
                for (int ni = 0; ni < 4; ++ni) {
#pragma unroll
                    for (int x = 0; x < acc[mi][ni].num_elements; ++x)
                        acc[mi][ni].x[x] = fast_tanh(acc[mi][ni].x[x]);
                    wmma::store_matrix_sync(
                        out + (size_t)(e0 + m0 + mi * 16) * 128 + n0 + ni * 16,
                        acc[mi][ni], 128, wmma::mem_row_major);
                }
        }
    }
}

extern "C" void kernel_launch(void* const* d_in, const int* in_sizes, int n_in,
                              void* d_out, int out_size) {
    const float* h   = (const float*)d_in[0];
    const float* dR  = (const float*)d_in[1];
    const int*   src = (const int*)  d_in[2];
    const int*   dst = (const int*)  d_in[3];
    const float* W1  = (const float*)d_in[4];
    const float* b1  = (const float*)d_in[5];
    const float* W2  = (const float*)d_in[6];
    const float* b2  = (const float*)d_in[7];
    float* out = (float*)d_out;

    convert_weights<<<288, 256>>>(W1, W2);

    cudaFuncSetAttribute(proj_kernel,
                         cudaFuncAttributeMaxDynamicSharedMemorySize, PJ_SMEM);
    cudaFuncSetAttribute(edge_kernel,
                         cudaFuncAttributeMaxDynamicSharedMemorySize, EK_SMEM);

    proj_kernel<<<(N_NODES + 127) / 128, 256, PJ_SMEM>>>(h);
    edge_kernel<<<GRID_P, 256, EK_SMEM>>>(dR, src, dst, W1, b1, b2, out);
}